// round 4
// baseline (speedup 1.0000x reference)
#include <cuda_runtime.h>
#include <math.h>

#define D_MODEL 1024
#define N_HEADS 16
#define HEAD_DIM 64
#define BATCH 4
#define SEQ 2048
#define M_TOTAL (BATCH * SEQ)   // 8192

// Scratch (device globals — allocation-free per harness rules)
__device__ float g_Q[BATCH * N_HEADS * SEQ * HEAD_DIM];   // [B,H,S,Dh]
__device__ float g_K[BATCH * N_HEADS * SEQ * HEAD_DIM];
__device__ float g_V[BATCH * N_HEADS * SEQ * HEAD_DIM];
__device__ float g_attn[M_TOTAL * D_MODEL];               // [B,S,D]

// ---------------------------------------------------------------------------
// SGEMM: C[m,n] = sum_k X[m,k] * W[n,k] + bias[n]
// X: [8192,1024] row-major, W: [1024,1024] row-major ([out,in]).
// mode 0/1/2: X = Xin, write to g_Q/g_K/g_V in [B,H,S,Dh] layout.
// mode 3:     X = g_attn (resolved DEVICE-side!), write Cout row-major.
// Tile: 128x128x8, 256 threads, 8x8 per-thread microtile.
// ---------------------------------------------------------------------------
__global__ __launch_bounds__(256) void proj_kernel(
    const float* __restrict__ Xin, const float* __restrict__ W,
    const float* __restrict__ bias, float* __restrict__ Cout, int mode)
{
    __shared__ float As[8][128];
    __shared__ float Bs[8][128];

    // CRITICAL: device-symbol scratch must be resolved in device code.
    const float* X = (mode == 3) ? g_attn : Xin;

    const int tid = threadIdx.x;
    const int m0 = blockIdx.y * 128;
    const int n0 = blockIdx.x * 128;
    const int tx = tid & 15;        // 0..15 -> n microtile
    const int ty = tid >> 4;        // 0..15 -> m microtile

    const int aRow = tid >> 1;      // 0..127
    const int aK   = (tid & 1) * 4; // 0 or 4

    const float* Xp = X + (size_t)(m0 + aRow) * D_MODEL;
    const float* Wp = W + (size_t)(n0 + aRow) * D_MODEL;

    float acc[8][8];
#pragma unroll
    for (int i = 0; i < 8; i++)
#pragma unroll
        for (int j = 0; j < 8; j++) acc[i][j] = 0.0f;

    for (int k0 = 0; k0 < D_MODEL; k0 += 8) {
        float4 av = *(const float4*)(Xp + k0 + aK);
        float4 bv = *(const float4*)(Wp + k0 + aK);
        __syncthreads();
        As[aK + 0][aRow] = av.x; As[aK + 1][aRow] = av.y;
        As[aK + 2][aRow] = av.z; As[aK + 3][aRow] = av.w;
        Bs[aK + 0][aRow] = bv.x; Bs[aK + 1][aRow] = bv.y;
        Bs[aK + 2][aRow] = bv.z; Bs[aK + 3][aRow] = bv.w;
        __syncthreads();

#pragma unroll
        for (int k = 0; k < 8; k++) {
            float a[8], b[8];
#pragma unroll
            for (int i = 0; i < 8; i++) a[i] = As[k][ty * 8 + i];
#pragma unroll
            for (int j = 0; j < 8; j++) b[j] = Bs[k][tx * 8 + j];
#pragma unroll
            for (int i = 0; i < 8; i++)
#pragma unroll
                for (int j = 0; j < 8; j++) acc[i][j] += a[i] * b[j];
        }
    }

    float* dst = (mode == 0) ? g_Q : (mode == 1) ? g_K : g_V;
#pragma unroll
    for (int i = 0; i < 8; i++) {
        const int m = m0 + ty * 8 + i;
#pragma unroll
        for (int j = 0; j < 8; j++) {
            const int n = n0 + tx * 8 + j;
            const float val = acc[i][j] + bias[n];
            if (mode == 3) {
                Cout[(size_t)m * D_MODEL + n] = val;
            } else {
                const int b = m >> 11, s = m & 2047;
                const int h = n >> 6,  dh = n & 63;
                dst[(((size_t)(b << 4) + h) * SEQ + s) * HEAD_DIM + dh] = val;
            }
        }
    }
}

// ---------------------------------------------------------------------------
// Flash attention, fp32. Per (b,h): Q[2048,64], K[2048,64], V[2048,64].
// Block: 256 threads = 8 warps. Each warp owns 8 query rows (Br=64).
// K tiles of Bc=64. Lane computes S[r][lane], S[r][lane+32].
// Writes output to g_attn[(b*S+s)*D + h*64 + dh].
// Dynamic smem: Qs 64x64 + Ks 64x65(pad) + Vs 64x64 + Ps 64x64 = 65792 B.
// ---------------------------------------------------------------------------
#define ATTN_SMEM_FLOATS (64 * 64 + 64 * 65 + 64 * 64 + 64 * 64)
#define ATTN_SMEM_BYTES  (ATTN_SMEM_FLOATS * 4)

__global__ __launch_bounds__(256) void attn_kernel()
{
    extern __shared__ float sm[];
    float* Qs = sm;                    // [64][64]  Qs[r*64+k]
    float* Ks = Qs + 64 * 64;          // [64][65]  Ks[c*65+k] (padded)
    float* Vs = Ks + 64 * 65;          // [64][64]  Vs[c*64+d]
    float* Ps = Vs + 64 * 64;          // [64][64]  Ps[r*64+c]

    const int tid  = threadIdx.x;
    const int warp = tid >> 5;
    const int lane = tid & 31;
    const int bh = blockIdx.y;         // 0..63
    const int q0 = blockIdx.x * 64;
    const float scale = 0.125f;        // 1/sqrt(64)

    const float* Qg = g_Q + (size_t)bh * SEQ * HEAD_DIM + (size_t)q0 * HEAD_DIM;
    const float* Kg = g_K + (size_t)bh * SEQ * HEAD_DIM;
    const float* Vg = g_V + (size_t)bh * SEQ * HEAD_DIM;

    // Load Q tile (contiguous, float4)
    for (int i = tid * 4; i < 64 * 64; i += 256 * 4)
        *(float4*)(Qs + i) = *(const float4*)(Qg + i);

    float m_run[8], l_run[8], acc0[8], acc1[8];
#pragma unroll
    for (int r = 0; r < 8; r++) {
        m_run[r] = -1e30f; l_run[r] = 0.0f; acc0[r] = 0.0f; acc1[r] = 0.0f;
    }

    for (int kc = 0; kc < SEQ; kc += 64) {
        __syncthreads();   // protect previous tile's Ks/Vs reads
        // Load K (padded rows) and V tiles
        for (int i = tid * 4; i < 64 * 64; i += 256 * 4) {
            float4 kt = *(const float4*)(Kg + kc * HEAD_DIM + i);
            float4 vt = *(const float4*)(Vg + kc * HEAD_DIM + i);
            const int c = i >> 6, k = i & 63;
            Ks[c * 65 + k + 0] = kt.x; Ks[c * 65 + k + 1] = kt.y;
            Ks[c * 65 + k + 2] = kt.z; Ks[c * 65 + k + 3] = kt.w;
            *(float4*)(Vs + i) = vt;
        }
        __syncthreads();

        // --- S = Q K^T for this warp's 8 rows, 2 cols per lane ---
        float s0[8], s1[8];
#pragma unroll
        for (int r = 0; r < 8; r++) { s0[r] = 0.0f; s1[r] = 0.0f; }
#pragma unroll 8
        for (int k = 0; k < 64; k++) {
            const float kv0 = Ks[lane * 65 + k];
            const float kv1 = Ks[(lane + 32) * 65 + k];
#pragma unroll
            for (int r = 0; r < 8; r++) {
                const float q = Qs[(warp * 8 + r) * 64 + k];
                s0[r] += q * kv0;
                s1[r] += q * kv1;
            }
        }

        // --- online softmax per row ---
#pragma unroll
        for (int r = 0; r < 8; r++) {
            const float v0 = s0[r] * scale, v1 = s1[r] * scale;
            float mx = fmaxf(v0, v1);
#pragma unroll
            for (int off = 16; off > 0; off >>= 1)
                mx = fmaxf(mx, __shfl_xor_sync(0xffffffffu, mx, off));
            const float mnew = fmaxf(m_run[r], mx);
            const float p0 = __expf(v0 - mnew);
            const float p1 = __expf(v1 - mnew);
            float ps = p0 + p1;
#pragma unroll
            for (int off = 16; off > 0; off >>= 1)
                ps += __shfl_xor_sync(0xffffffffu, ps, off);
            const float alpha = __expf(m_run[r] - mnew);
            l_run[r] = l_run[r] * alpha + ps;
            m_run[r] = mnew;
            acc0[r] *= alpha;
            acc1[r] *= alpha;
            Ps[(warp * 8 + r) * 64 + lane]      = p0;
            Ps[(warp * 8 + r) * 64 + lane + 32] = p1;
        }
        __syncwarp();      // Ps written/read only within this warp's rows

        // --- O += P V ---
#pragma unroll 8
        for (int c = 0; c < 64; c++) {
            const float v0 = Vs[c * 64 + lane];
            const float v1 = Vs[c * 64 + lane + 32];
#pragma unroll
            for (int r = 0; r < 8; r++) {
                const float p = Ps[(warp * 8 + r) * 64 + c];
                acc0[r] += p * v0;
                acc1[r] += p * v1;
            }
        }
    }

    // Epilogue: normalize and scatter into [B,S,D] layout
    const int b = bh >> 4, h = bh & 15;
#pragma unroll
    for (int r = 0; r < 8; r++) {
        const int row = warp * 8 + r;
        const float inv = 1.0f / l_run[r];
        const int sg = q0 + row;
        float* o = g_attn + ((size_t)(b * SEQ + sg)) * D_MODEL + h * HEAD_DIM;
        o[lane]      = acc0[r] * inv;
        o[lane + 32] = acc1[r] * inv;
    }
}

// ---------------------------------------------------------------------------
extern "C" void kernel_launch(void* const* d_in, const int* in_sizes, int n_in,
                              void* d_out, int out_size)
{
    (void)in_sizes; (void)n_in; (void)out_size;
    const float* query = (const float*)d_in[0];
    const float* key   = (const float*)d_in[1];
    const float* value = (const float*)d_in[2];
    const float* Wq    = (const float*)d_in[3];
    const float* bq    = (const float*)d_in[4];
    const float* Wk    = (const float*)d_in[5];
    const float* bk    = (const float*)d_in[6];
    const float* Wv    = (const float*)d_in[7];
    const float* bv    = (const float*)d_in[8];
    const float* Wo    = (const float*)d_in[9];
    const float* bo    = (const float*)d_in[10];
    float* out = (float*)d_out;

    cudaFuncSetAttribute(attn_kernel,
                         cudaFuncAttributeMaxDynamicSharedMemorySize,
                         ATTN_SMEM_BYTES);

    dim3 ggrid(D_MODEL / 128, M_TOTAL / 128);   // (8, 64)
    proj_kernel<<<ggrid, 256>>>(query, Wq, bq, nullptr, 0);
    proj_kernel<<<ggrid, 256>>>(key,   Wk, bk, nullptr, 1);
    proj_kernel<<<ggrid, 256>>>(value, Wv, bv, nullptr, 2);

    dim3 agrid(SEQ / 64, BATCH * N_HEADS);      // (32, 64)
    attn_kernel<<<agrid, 256, ATTN_SMEM_BYTES>>>();

    // Output projection: reads g_attn (device-side), writes d_out.
    proj_kernel<<<ggrid, 256>>>(nullptr, Wo, bo, out, 3);
}

// round 12
// speedup vs baseline: 1.7000x; 1.7000x over previous
#include <cuda_runtime.h>
#include <stdint.h>
#include <math.h>

#define D_MODEL 1024
#define N_HEADS 16
#define HEAD_DIM 64
#define BATCH 4
#define SEQ 2048
#define M_TOTAL (BATCH * SEQ)   // 8192

// Scratch (device globals — allocation-free per harness rules)
__device__ float g_Q[BATCH * N_HEADS * SEQ * HEAD_DIM];   // [B,H,S,Dh]
__device__ float g_K[BATCH * N_HEADS * SEQ * HEAD_DIM];
__device__ float g_V[BATCH * N_HEADS * SEQ * HEAD_DIM];
__device__ float g_attn[M_TOTAL * D_MODEL];               // [B,S,D]

// ===========================================================================
// Portable tensor-core helpers (mma.sync, sm_80+ PTX — no 'a'-gated features)
// ===========================================================================
__device__ __forceinline__ uint32_t f2tf32(float x) {
    uint32_t r;
    asm("cvt.rna.tf32.f32 %0, %1;" : "=r"(r) : "f"(x));
    return r;
}

// D(16x8) += A(16x8, row) * B(8x8, col)   tf32 inputs, fp32 accumulate
__device__ __forceinline__ void mma_tf32(float c[4],
                                         uint32_t a0, uint32_t a1,
                                         uint32_t a2, uint32_t a3,
                                         uint32_t b0, uint32_t b1)
{
    asm volatile(
        "mma.sync.aligned.m16n8k8.row.col.f32.tf32.tf32.f32 "
        "{%0,%1,%2,%3}, {%4,%5,%6,%7}, {%8,%9}, {%0,%1,%2,%3};"
        : "+f"(c[0]), "+f"(c[1]), "+f"(c[2]), "+f"(c[3])
        : "r"(a0), "r"(a1), "r"(a2), "r"(a3), "r"(b0), "r"(b1));
}

// ===========================================================================
// tf32 mma.sync GEMM: C[m,n] = sum_k X[m,k]*W[n,k] + bias[n]
// X: [8192,1024] row-major, W: [1024,1024] row-major ([out,in]).
// mode 0/1/2: X = Xin, scatter into g_Q/g_K/g_V [B,H,S,Dh].
// mode 3:     X = g_attn (device-side resolve), write Cout row-major.
//
// CTA tile 128x128, 256 thr = 8 warps (2 m x 4 n), warp tile 64x32.
// K-chunks of 32; SMEM [128][36] pad -> conflict-free frag LDS + STS.128.
// Register prefetch of chunk j+1 overlaps LDG latency with MMA compute.
// ===========================================================================
#define PAD 36

__global__ __launch_bounds__(256) void proj_mma_kernel(
    const float* __restrict__ Xin, const float* __restrict__ W,
    const float* __restrict__ bias, float* __restrict__ Cout, int mode)
{
    __shared__ uint32_t As[128 * PAD];
    __shared__ uint32_t Bs[128 * PAD];

    const float* X = (mode == 3) ? g_attn : Xin;

    const int tid  = threadIdx.x;
    const int lane = tid & 31;
    const int wid  = tid >> 5;
    const int wm   = wid & 1;       // 0..1 -> 64-row half
    const int wn   = wid >> 1;      // 0..3 -> 32-col quarter
    const int m0 = blockIdx.y * 128;
    const int n0 = blockIdx.x * 128;

    const int grp = lane >> 2;      // 0..7
    const int qid = lane & 3;       // 0..3

    float acc[4][4][4];
#pragma unroll
    for (int mt = 0; mt < 4; mt++)
#pragma unroll
        for (int nt = 0; nt < 4; nt++)
#pragma unroll
            for (int e = 0; e < 4; e++) acc[mt][nt][e] = 0.0f;

    // Per-thread staging slots: 4 float4 per tile (1024 float4 / 256 thr).
    int rowi[4], c4i[4];
#pragma unroll
    for (int i = 0; i < 4; i++) {
        const int f = tid + i * 256;
        rowi[i] = f >> 3;           // 0..127
        c4i[i]  = (f & 7) * 4;      // 0,4,...,28
    }

    float4 pa[4], pb[4];
#pragma unroll
    for (int i = 0; i < 4; i++) {
        pa[i] = *(const float4*)(X + (size_t)(m0 + rowi[i]) * D_MODEL + c4i[i]);
        pb[i] = *(const float4*)(W + (size_t)(n0 + rowi[i]) * D_MODEL + c4i[i]);
    }

    for (int j = 0; j < 32; j++) {
        // Store prefetched chunk j into SMEM (tf32 convert, STS.128, no conflicts).
#pragma unroll
        for (int i = 0; i < 4; i++) {
            uint4 at = make_uint4(f2tf32(pa[i].x), f2tf32(pa[i].y),
                                  f2tf32(pa[i].z), f2tf32(pa[i].w));
            uint4 bt = make_uint4(f2tf32(pb[i].x), f2tf32(pb[i].y),
                                  f2tf32(pb[i].z), f2tf32(pb[i].w));
            *(uint4*)(As + rowi[i] * PAD + c4i[i]) = at;
            *(uint4*)(Bs + rowi[i] * PAD + c4i[i]) = bt;
        }
        __syncthreads();

        // Prefetch chunk j+1 (LDG latency hides under the MMA block below).
        if (j < 31) {
            const int k0n = (j + 1) * 32;
#pragma unroll
            for (int i = 0; i < 4; i++) {
                pa[i] = *(const float4*)(X + (size_t)(m0 + rowi[i]) * D_MODEL + k0n + c4i[i]);
                pb[i] = *(const float4*)(W + (size_t)(n0 + rowi[i]) * D_MODEL + k0n + c4i[i]);
            }
        }

        // Compute: 4 k-steps of 8, 4x4 fragment tiles per warp.
#pragma unroll
        for (int ks = 0; ks < 4; ks++) {
            const int kc = ks * 8 + qid;
            uint32_t af[4][4];
#pragma unroll
            for (int mt = 0; mt < 4; mt++) {
                const int ar = (wm * 64 + mt * 16 + grp) * PAD;
                af[mt][0] = As[ar + kc];
                af[mt][1] = As[ar + 8 * PAD + kc];
                af[mt][2] = As[ar + kc + 4];
                af[mt][3] = As[ar + 8 * PAD + kc + 4];
            }
            uint32_t bf[4][2];
#pragma unroll
            for (int nt = 0; nt < 4; nt++) {
                const int br = (wn * 32 + nt * 8 + grp) * PAD;
                bf[nt][0] = Bs[br + kc];
                bf[nt][1] = Bs[br + kc + 4];
            }
#pragma unroll
            for (int mt = 0; mt < 4; mt++)
#pragma unroll
                for (int nt = 0; nt < 4; nt++)
                    mma_tf32(acc[mt][nt], af[mt][0], af[mt][1], af[mt][2],
                             af[mt][3], bf[nt][0], bf[nt][1]);
        }
        __syncthreads();
    }

    // Epilogue: add bias, write float2 pairs.
    float* dst = (mode == 0) ? g_Q : (mode == 1) ? g_K : g_V;
#pragma unroll
    for (int mt = 0; mt < 4; mt++) {
#pragma unroll
        for (int nt = 0; nt < 4; nt++) {
            const int n = n0 + wn * 32 + nt * 8 + qid * 2;
            const float2 b2 = *(const float2*)(bias + n);
#pragma unroll
            for (int half = 0; half < 2; half++) {
                const int m = m0 + wm * 64 + mt * 16 + grp + half * 8;
                float2 v;
                v.x = acc[mt][nt][half * 2 + 0] + b2.x;
                v.y = acc[mt][nt][half * 2 + 1] + b2.y;
                if (mode == 3) {
                    *(float2*)(Cout + (size_t)m * D_MODEL + n) = v;
                } else {
                    const int bb = m >> 11, s = m & 2047;
                    const int h  = n >> 6,  dh = n & 63;
                    *(float2*)(dst + (((size_t)(bb * N_HEADS + h) * SEQ + s)
                                      * HEAD_DIM) + dh) = v;
                }
            }
        }
    }
}

// ---------------------------------------------------------------------------
// Flash attention, fp32 (unchanged from the 4584us passing kernel).
// ---------------------------------------------------------------------------
#define ATTN_SMEM_FLOATS (64 * 64 + 64 * 65 + 64 * 64 + 64 * 64)
#define ATTN_SMEM_BYTES  (ATTN_SMEM_FLOATS * 4)

__global__ __launch_bounds__(256) void attn_kernel()
{
    extern __shared__ float sm[];
    float* Qs = sm;                    // [64][64]
    float* Ks = Qs + 64 * 64;          // [64][65] padded
    float* Vs = Ks + 64 * 65;          // [64][64]
    float* Ps = Vs + 64 * 64;          // [64][64]

    const int tid  = threadIdx.x;
    const int warp = tid >> 5;
    const int lane = tid & 31;
    const int bh = blockIdx.y;
    const int q0 = blockIdx.x * 64;
    const float scale = 0.125f;

    const float* Qg = g_Q + (size_t)bh * SEQ * HEAD_DIM + (size_t)q0 * HEAD_DIM;
    const float* Kg = g_K + (size_t)bh * SEQ * HEAD_DIM;
    const float* Vg = g_V + (size_t)bh * SEQ * HEAD_DIM;

    for (int i = tid * 4; i < 64 * 64; i += 256 * 4)
        *(float4*)(Qs + i) = *(const float4*)(Qg + i);

    float m_run[8], l_run[8], acc0[8], acc1[8];
#pragma unroll
    for (int r = 0; r < 8; r++) {
        m_run[r] = -1e30f; l_run[r] = 0.0f; acc0[r] = 0.0f; acc1[r] = 0.0f;
    }

    for (int kc = 0; kc < SEQ; kc += 64) {
        __syncthreads();
        for (int i = tid * 4; i < 64 * 64; i += 256 * 4) {
            float4 kt = *(const float4*)(Kg + kc * HEAD_DIM + i);
            float4 vt = *(const float4*)(Vg + kc * HEAD_DIM + i);
            const int c = i >> 6, k = i & 63;
            Ks[c * 65 + k + 0] = kt.x; Ks[c * 65 + k + 1] = kt.y;
            Ks[c * 65 + k + 2] = kt.z; Ks[c * 65 + k + 3] = kt.w;
            *(float4*)(Vs + i) = vt;
        }
        __syncthreads();

        float s0[8], s1[8];
#pragma unroll
        for (int r = 0; r < 8; r++) { s0[r] = 0.0f; s1[r] = 0.0f; }
#pragma unroll 8
        for (int k = 0; k < 64; k++) {
            const float kv0 = Ks[lane * 65 + k];
            const float kv1 = Ks[(lane + 32) * 65 + k];
#pragma unroll
            for (int r = 0; r < 8; r++) {
                const float q = Qs[(warp * 8 + r) * 64 + k];
                s0[r] += q * kv0;
                s1[r] += q * kv1;
            }
        }

#pragma unroll
        for (int r = 0; r < 8; r++) {
            const float v0 = s0[r] * scale, v1 = s1[r] * scale;
            float mx = fmaxf(v0, v1);
#pragma unroll
            for (int off = 16; off > 0; off >>= 1)
                mx = fmaxf(mx, __shfl_xor_sync(0xffffffffu, mx, off));
            const float mnew = fmaxf(m_run[r], mx);
            const float p0 = __expf(v0 - mnew);
            const float p1 = __expf(v1 - mnew);
            float ps = p0 + p1;
#pragma unroll
            for (int off = 16; off > 0; off >>= 1)
                ps += __shfl_xor_sync(0xffffffffu, ps, off);
            const float alpha = __expf(m_run[r] - mnew);
            l_run[r] = l_run[r] * alpha + ps;
            m_run[r] = mnew;
            acc0[r] *= alpha;
            acc1[r] *= alpha;
            Ps[(warp * 8 + r) * 64 + lane]      = p0;
            Ps[(warp * 8 + r) * 64 + lane + 32] = p1;
        }
        __syncwarp();

#pragma unroll 8
        for (int c = 0; c < 64; c++) {
            const float v0 = Vs[c * 64 + lane];
            const float v1 = Vs[c * 64 + lane + 32];
#pragma unroll
            for (int r = 0; r < 8; r++) {
                const float p = Ps[(warp * 8 + r) * 64 + c];
                acc0[r] += p * v0;
                acc1[r] += p * v1;
            }
        }
    }

    const int b = bh >> 4, h = bh & 15;
#pragma unroll
    for (int r = 0; r < 8; r++) {
        const int row = warp * 8 + r;
        const float inv = 1.0f / l_run[r];
        const int sg = q0 + row;
        float* o = g_attn + ((size_t)(b * SEQ + sg)) * D_MODEL + h * HEAD_DIM;
        o[lane]      = acc0[r] * inv;
        o[lane + 32] = acc1[r] * inv;
    }
}

// ---------------------------------------------------------------------------
extern "C" void kernel_launch(void* const* d_in, const int* in_sizes, int n_in,
                              void* d_out, int out_size)
{
    (void)in_sizes; (void)n_in; (void)out_size;
    const float* query = (const float*)d_in[0];
    const float* key   = (const float*)d_in[1];
    const float* value = (const float*)d_in[2];
    const float* Wq    = (const float*)d_in[3];
    const float* bq    = (const float*)d_in[4];
    const float* Wk    = (const float*)d_in[5];
    const float* bk    = (const float*)d_in[6];
    const float* Wv    = (const float*)d_in[7];
    const float* bv    = (const float*)d_in[8];
    const float* Wo    = (const float*)d_in[9];
    const float* bo    = (const float*)d_in[10];
    float* out = (float*)d_out;

    cudaFuncSetAttribute(attn_kernel,
                         cudaFuncAttributeMaxDynamicSharedMemorySize,
                         ATTN_SMEM_BYTES);

    dim3 ggrid(D_MODEL / 128, M_TOTAL / 128);   // (8, 64)
    proj_mma_kernel<<<ggrid, 256>>>(query, Wq, bq, nullptr, 0);
    proj_mma_kernel<<<ggrid, 256>>>(key,   Wk, bk, nullptr, 1);
    proj_mma_kernel<<<ggrid, 256>>>(value, Wv, bv, nullptr, 2);

    dim3 agrid(SEQ / 64, BATCH * N_HEADS);      // (32, 64)
    attn_kernel<<<agrid, 256, ATTN_SMEM_BYTES>>>();

    proj_mma_kernel<<<ggrid, 256>>>(nullptr, Wo, bo, out, 3);
}

// round 13
// speedup vs baseline: 2.8729x; 1.6899x over previous
#include <cuda_runtime.h>
#include <stdint.h>
#include <math.h>

#define D_MODEL 1024
#define N_HEADS 16
#define HEAD_DIM 64
#define BATCH 4
#define SEQ 2048
#define M_TOTAL (BATCH * SEQ)   // 8192

// Scratch (device globals — allocation-free per harness rules)
__device__ float g_Q[BATCH * N_HEADS * SEQ * HEAD_DIM];   // [B,H,S,Dh]
__device__ float g_K[BATCH * N_HEADS * SEQ * HEAD_DIM];
__device__ float g_V[BATCH * N_HEADS * SEQ * HEAD_DIM];
__device__ float g_attn[M_TOTAL * D_MODEL];               // [B,S,D]

// ===========================================================================
// Portable tensor-core helpers (mma.sync, sm_80+ PTX — no 'a'-gated features)
// ===========================================================================
__device__ __forceinline__ uint32_t f2tf32(float x) {
    uint32_t r;
    asm("cvt.rna.tf32.f32 %0, %1;" : "=r"(r) : "f"(x));
    return r;
}

// D(16x8) += A(16x8, row) * B(8x8, col)   tf32 inputs, fp32 accumulate
__device__ __forceinline__ void mma_tf32(float c[4],
                                         uint32_t a0, uint32_t a1,
                                         uint32_t a2, uint32_t a3,
                                         uint32_t b0, uint32_t b1)
{
    asm volatile(
        "mma.sync.aligned.m16n8k8.row.col.f32.tf32.tf32.f32 "
        "{%0,%1,%2,%3}, {%4,%5,%6,%7}, {%8,%9}, {%0,%1,%2,%3};"
        : "+f"(c[0]), "+f"(c[1]), "+f"(c[2]), "+f"(c[3])
        : "r"(a0), "r"(a1), "r"(a2), "r"(a3), "r"(b0), "r"(b1));
}

__device__ __forceinline__ void mma_tf32_f(float c[4],
                                           float a0, float a1,
                                           float a2, float a3,
                                           float b0, float b1)
{
    mma_tf32(c, __float_as_uint(a0), __float_as_uint(a1),
                __float_as_uint(a2), __float_as_uint(a3),
                __float_as_uint(b0), __float_as_uint(b1));
}

// ===========================================================================
// tf32 mma.sync GEMM (unchanged from the 2697us passing kernel).
// C[m,n] = sum_k X[m,k]*W[n,k] + bias[n]
// ===========================================================================
#define PAD 36

__global__ __launch_bounds__(256) void proj_mma_kernel(
    const float* __restrict__ Xin, const float* __restrict__ W,
    const float* __restrict__ bias, float* __restrict__ Cout, int mode)
{
    __shared__ uint32_t As[128 * PAD];
    __shared__ uint32_t Bs[128 * PAD];

    const float* X = (mode == 3) ? g_attn : Xin;

    const int tid  = threadIdx.x;
    const int lane = tid & 31;
    const int wid  = tid >> 5;
    const int wm   = wid & 1;
    const int wn   = wid >> 1;
    const int m0 = blockIdx.y * 128;
    const int n0 = blockIdx.x * 128;

    const int grp = lane >> 2;
    const int qid = lane & 3;

    float acc[4][4][4];
#pragma unroll
    for (int mt = 0; mt < 4; mt++)
#pragma unroll
        for (int nt = 0; nt < 4; nt++)
#pragma unroll
            for (int e = 0; e < 4; e++) acc[mt][nt][e] = 0.0f;

    int rowi[4], c4i[4];
#pragma unroll
    for (int i = 0; i < 4; i++) {
        const int f = tid + i * 256;
        rowi[i] = f >> 3;
        c4i[i]  = (f & 7) * 4;
    }

    float4 pa[4], pb[4];
#pragma unroll
    for (int i = 0; i < 4; i++) {
        pa[i] = *(const float4*)(X + (size_t)(m0 + rowi[i]) * D_MODEL + c4i[i]);
        pb[i] = *(const float4*)(W + (size_t)(n0 + rowi[i]) * D_MODEL + c4i[i]);
    }

    for (int j = 0; j < 32; j++) {
#pragma unroll
        for (int i = 0; i < 4; i++) {
            uint4 at = make_uint4(f2tf32(pa[i].x), f2tf32(pa[i].y),
                                  f2tf32(pa[i].z), f2tf32(pa[i].w));
            uint4 bt = make_uint4(f2tf32(pb[i].x), f2tf32(pb[i].y),
                                  f2tf32(pb[i].z), f2tf32(pb[i].w));
            *(uint4*)(As + rowi[i] * PAD + c4i[i]) = at;
            *(uint4*)(Bs + rowi[i] * PAD + c4i[i]) = bt;
        }
        __syncthreads();

        if (j < 31) {
            const int k0n = (j + 1) * 32;
#pragma unroll
            for (int i = 0; i < 4; i++) {
                pa[i] = *(const float4*)(X + (size_t)(m0 + rowi[i]) * D_MODEL + k0n + c4i[i]);
                pb[i] = *(const float4*)(W + (size_t)(n0 + rowi[i]) * D_MODEL + k0n + c4i[i]);
            }
        }

#pragma unroll
        for (int ks = 0; ks < 4; ks++) {
            const int kc = ks * 8 + qid;
            uint32_t af[4][4];
#pragma unroll
            for (int mt = 0; mt < 4; mt++) {
                const int ar = (wm * 64 + mt * 16 + grp) * PAD;
                af[mt][0] = As[ar + kc];
                af[mt][1] = As[ar + 8 * PAD + kc];
                af[mt][2] = As[ar + kc + 4];
                af[mt][3] = As[ar + 8 * PAD + kc + 4];
            }
            uint32_t bf[4][2];
#pragma unroll
            for (int nt = 0; nt < 4; nt++) {
                const int br = (wn * 32 + nt * 8 + grp) * PAD;
                bf[nt][0] = Bs[br + kc];
                bf[nt][1] = Bs[br + kc + 4];
            }
#pragma unroll
            for (int mt = 0; mt < 4; mt++)
#pragma unroll
                for (int nt = 0; nt < 4; nt++)
                    mma_tf32(acc[mt][nt], af[mt][0], af[mt][1], af[mt][2],
                             af[mt][3], bf[nt][0], bf[nt][1]);
        }
        __syncthreads();
    }

    float* dst = (mode == 0) ? g_Q : (mode == 1) ? g_K : g_V;
#pragma unroll
    for (int mt = 0; mt < 4; mt++) {
#pragma unroll
        for (int nt = 0; nt < 4; nt++) {
            const int n = n0 + wn * 32 + nt * 8 + qid * 2;
            const float2 b2 = *(const float2*)(bias + n);
#pragma unroll
            for (int half = 0; half < 2; half++) {
                const int m = m0 + wm * 64 + mt * 16 + grp + half * 8;
                float2 v;
                v.x = acc[mt][nt][half * 2 + 0] + b2.x;
                v.y = acc[mt][nt][half * 2 + 1] + b2.y;
                if (mode == 3) {
                    *(float2*)(Cout + (size_t)m * D_MODEL + n) = v;
                } else {
                    const int bb = m >> 11, s = m & 2047;
                    const int h  = n >> 6,  dh = n & 63;
                    *(float2*)(dst + (((size_t)(bb * N_HEADS + h) * SEQ + s)
                                      * HEAD_DIM) + dh) = v;
                }
            }
        }
    }
}

// ===========================================================================
// Tensor-core flash attention (tf32 mma.sync).
// Per (b,h): Q[2048,64], K[2048,64], V[2048,64].
// CTA: 128 thr = 4 warps; Br=64 (16 q-rows per warp), Bc=64.
// QK^T: split-precision 3xTF32 (fp32-accurate scores).
// PV:   plain tf32; row-sum l computed from tf32-rounded P so P-rounding
//       cancels in normalization.
// SMEM stride 68 -> conflict-free fragment loads (banks 4*grp+qid distinct).
// ===========================================================================
#define AT_PAD  68
#define AT_TILE (64 * AT_PAD)
#define ATTN_TC_SMEM (6 * AT_TILE * 4)   // 104448 B -> 2 CTAs/SM

__global__ __launch_bounds__(128) void attn_tc_kernel()
{
    extern __shared__ float smf[];
    float* Qhi = smf;
    float* Qlo = Qhi + AT_TILE;
    float* Khi = Qlo + AT_TILE;
    float* Klo = Khi + AT_TILE;
    float* Vs  = Klo + AT_TILE;   // row-major [c][d], tf32 values
    float* Ps  = Vs  + AT_TILE;   // [r][c], tf32 values

    const int tid  = threadIdx.x;
    const int warp = tid >> 5;
    const int lane = tid & 31;
    const int grp  = lane >> 2;   // 0..7
    const int qid  = lane & 3;    // 0..3
    const int bh = blockIdx.y;
    const int q0 = blockIdx.x * 64;

    const float* Qg = g_Q + (size_t)bh * SEQ * HEAD_DIM + (size_t)q0 * HEAD_DIM;
    const float* Kg = g_K + (size_t)bh * SEQ * HEAD_DIM;
    const float* Vg = g_V + (size_t)bh * SEQ * HEAD_DIM;

    // Load Q tile once: scale by 1/8 (exact), split into tf32 hi + lo.
#pragma unroll
    for (int i = 0; i < 8; i++) {
        const int f = tid + i * 128;          // 0..1023 float4 slots
        const int row = f >> 4, c4 = (f & 15) * 4;
        float4 q = *(const float4*)(Qg + row * 64 + c4);
        q.x *= 0.125f; q.y *= 0.125f; q.z *= 0.125f; q.w *= 0.125f;
        float4 hi, lo;
        hi.x = __uint_as_float(f2tf32(q.x)); lo.x = __uint_as_float(f2tf32(q.x - hi.x));
        hi.y = __uint_as_float(f2tf32(q.y)); lo.y = __uint_as_float(f2tf32(q.y - hi.y));
        hi.z = __uint_as_float(f2tf32(q.z)); lo.z = __uint_as_float(f2tf32(q.z - hi.z));
        hi.w = __uint_as_float(f2tf32(q.w)); lo.w = __uint_as_float(f2tf32(q.w - hi.w));
        *(float4*)(Qhi + row * AT_PAD + c4) = hi;
        *(float4*)(Qlo + row * AT_PAD + c4) = lo;
    }

    float m_run[2] = { -1e30f, -1e30f };
    float l_run[2] = { 0.0f, 0.0f };
    float oacc[8][4];
#pragma unroll
    for (int nt = 0; nt < 8; nt++)
#pragma unroll
        for (int e = 0; e < 4; e++) oacc[nt][e] = 0.0f;

    const int arow = (warp * 16 + grp) * AT_PAD;   // this thread's A-frag row base

    for (int kt = 0; kt < SEQ / 64; kt++) {
        // ---- gmem -> regs ----
        float4 kv[8], vv[8];
#pragma unroll
        for (int i = 0; i < 8; i++) {
            const int f = tid + i * 128;
            const int row = f >> 4, c4 = (f & 15) * 4;
            kv[i] = *(const float4*)(Kg + (size_t)(kt * 64 + row) * 64 + c4);
            vv[i] = *(const float4*)(Vg + (size_t)(kt * 64 + row) * 64 + c4);
        }
        __syncthreads();   // all warps done reading previous K/V/Ps tiles
        // ---- regs -> smem: split K, convert V ----
#pragma unroll
        for (int i = 0; i < 8; i++) {
            const int f = tid + i * 128;
            const int row = f >> 4, c4 = (f & 15) * 4;
            float4 hi, lo;
            hi.x = __uint_as_float(f2tf32(kv[i].x)); lo.x = __uint_as_float(f2tf32(kv[i].x - hi.x));
            hi.y = __uint_as_float(f2tf32(kv[i].y)); lo.y = __uint_as_float(f2tf32(kv[i].y - hi.y));
            hi.z = __uint_as_float(f2tf32(kv[i].z)); lo.z = __uint_as_float(f2tf32(kv[i].z - hi.z));
            hi.w = __uint_as_float(f2tf32(kv[i].w)); lo.w = __uint_as_float(f2tf32(kv[i].w - hi.w));
            *(float4*)(Khi + row * AT_PAD + c4) = hi;
            *(float4*)(Klo + row * AT_PAD + c4) = lo;
            float4 vt;
            vt.x = __uint_as_float(f2tf32(vv[i].x));
            vt.y = __uint_as_float(f2tf32(vv[i].y));
            vt.z = __uint_as_float(f2tf32(vv[i].z));
            vt.w = __uint_as_float(f2tf32(vv[i].w));
            *(float4*)(Vs + row * AT_PAD + c4) = vt;
        }
        __syncthreads();

        // ---- S = (Q/8) K^T, split 3xTF32 ----
        float sacc[8][4];
#pragma unroll
        for (int nt = 0; nt < 8; nt++)
#pragma unroll
            for (int e = 0; e < 4; e++) sacc[nt][e] = 0.0f;

#pragma unroll
        for (int ks = 0; ks < 8; ks++) {
            const int kc = ks * 8 + qid;
            const float ah0 = Qhi[arow + kc],            ah1 = Qhi[arow + 8 * AT_PAD + kc];
            const float ah2 = Qhi[arow + kc + 4],        ah3 = Qhi[arow + 8 * AT_PAD + kc + 4];
            const float al0 = Qlo[arow + kc],            al1 = Qlo[arow + 8 * AT_PAD + kc];
            const float al2 = Qlo[arow + kc + 4],        al3 = Qlo[arow + 8 * AT_PAD + kc + 4];
#pragma unroll
            for (int nt = 0; nt < 8; nt++) {
                const int br = (nt * 8 + grp) * AT_PAD;
                const float bh0 = Khi[br + kc], bh1 = Khi[br + kc + 4];
                const float bl0 = Klo[br + kc], bl1 = Klo[br + kc + 4];
                mma_tf32_f(sacc[nt], al0, al1, al2, al3, bh0, bh1);  // Qlo*Khi
                mma_tf32_f(sacc[nt], ah0, ah1, ah2, ah3, bl0, bl1);  // Qhi*Klo
                mma_tf32_f(sacc[nt], ah0, ah1, ah2, ah3, bh0, bh1);  // Qhi*Khi
            }
        }

        // ---- online softmax (rows grp, grp+8 of this warp's 16) ----
        float mx0 = -1e30f, mx1 = -1e30f;
#pragma unroll
        for (int nt = 0; nt < 8; nt++) {
            mx0 = fmaxf(mx0, fmaxf(sacc[nt][0], sacc[nt][1]));
            mx1 = fmaxf(mx1, fmaxf(sacc[nt][2], sacc[nt][3]));
        }
        mx0 = fmaxf(mx0, __shfl_xor_sync(0xffffffffu, mx0, 1));
        mx0 = fmaxf(mx0, __shfl_xor_sync(0xffffffffu, mx0, 2));
        mx1 = fmaxf(mx1, __shfl_xor_sync(0xffffffffu, mx1, 1));
        mx1 = fmaxf(mx1, __shfl_xor_sync(0xffffffffu, mx1, 2));

        const float mn0 = fmaxf(m_run[0], mx0);
        const float mn1 = fmaxf(m_run[1], mx1);
        const float alpha0 = __expf(m_run[0] - mn0);
        const float alpha1 = __expf(m_run[1] - mn1);
        m_run[0] = mn0; m_run[1] = mn1;

        float ls0 = 0.0f, ls1 = 0.0f;
#pragma unroll
        for (int nt = 0; nt < 8; nt++) {
            const float p0 = __uint_as_float(f2tf32(__expf(sacc[nt][0] - mn0)));
            const float p1 = __uint_as_float(f2tf32(__expf(sacc[nt][1] - mn0)));
            const float p2 = __uint_as_float(f2tf32(__expf(sacc[nt][2] - mn1)));
            const float p3 = __uint_as_float(f2tf32(__expf(sacc[nt][3] - mn1)));
            ls0 += p0 + p1;
            ls1 += p2 + p3;
            *(float2*)(Ps + arow + nt * 8 + 2 * qid)               = make_float2(p0, p1);
            *(float2*)(Ps + arow + 8 * AT_PAD + nt * 8 + 2 * qid)  = make_float2(p2, p3);
        }
        ls0 += __shfl_xor_sync(0xffffffffu, ls0, 1);
        ls0 += __shfl_xor_sync(0xffffffffu, ls0, 2);
        ls1 += __shfl_xor_sync(0xffffffffu, ls1, 1);
        ls1 += __shfl_xor_sync(0xffffffffu, ls1, 2);
        l_run[0] = l_run[0] * alpha0 + ls0;
        l_run[1] = l_run[1] * alpha1 + ls1;

#pragma unroll
        for (int nt = 0; nt < 8; nt++) {
            oacc[nt][0] *= alpha0; oacc[nt][1] *= alpha0;
            oacc[nt][2] *= alpha1; oacc[nt][3] *= alpha1;
        }
        __syncwarp();   // Ps rows are warp-private; order stores before loads

        // ---- O += P V ----
#pragma unroll
        for (int ks = 0; ks < 8; ks++) {
            const int kc = ks * 8 + qid;
            const float a0 = Ps[arow + kc],     a1 = Ps[arow + 8 * AT_PAD + kc];
            const float a2 = Ps[arow + kc + 4], a3 = Ps[arow + 8 * AT_PAD + kc + 4];
#pragma unroll
            for (int nt = 0; nt < 8; nt++) {
                const float b0 = Vs[(ks * 8 + qid) * AT_PAD + nt * 8 + grp];
                const float b1 = Vs[(ks * 8 + qid + 4) * AT_PAD + nt * 8 + grp];
                mma_tf32_f(oacc[nt], a0, a1, a2, a3, b0, b1);
            }
        }
    }

    // ---- epilogue: normalize, scatter into [B,S,D] ----
    const float inv0 = 1.0f / l_run[0];
    const float inv1 = 1.0f / l_run[1];
    const int b = bh >> 4, h = bh & 15;
    const int row0 = q0 + warp * 16 + grp;
    const int row1 = row0 + 8;
    float* o0 = g_attn + ((size_t)(b * SEQ + row0)) * D_MODEL + h * HEAD_DIM;
    float* o1 = g_attn + ((size_t)(b * SEQ + row1)) * D_MODEL + h * HEAD_DIM;
#pragma unroll
    for (int nt = 0; nt < 8; nt++) {
        const int d = nt * 8 + 2 * qid;
        *(float2*)(o0 + d) = make_float2(oacc[nt][0] * inv0, oacc[nt][1] * inv0);
        *(float2*)(o1 + d) = make_float2(oacc[nt][2] * inv1, oacc[nt][3] * inv1);
    }
}

// ---------------------------------------------------------------------------
extern "C" void kernel_launch(void* const* d_in, const int* in_sizes, int n_in,
                              void* d_out, int out_size)
{
    (void)in_sizes; (void)n_in; (void)out_size;
    const float* query = (const float*)d_in[0];
    const float* key   = (const float*)d_in[1];
    const float* value = (const float*)d_in[2];
    const float* Wq    = (const float*)d_in[3];
    const float* bq    = (const float*)d_in[4];
    const float* Wk    = (const float*)d_in[5];
    const float* bk    = (const float*)d_in[6];
    const float* Wv    = (const float*)d_in[7];
    const float* bv    = (const float*)d_in[8];
    const float* Wo    = (const float*)d_in[9];
    const float* bo    = (const float*)d_in[10];
    float* out = (float*)d_out;

    cudaFuncSetAttribute(attn_tc_kernel,
                         cudaFuncAttributeMaxDynamicSharedMemorySize,
                         ATTN_TC_SMEM);

    dim3 ggrid(D_MODEL / 128, M_TOTAL / 128);   // (8, 64)
    proj_mma_kernel<<<ggrid, 256>>>(query, Wq, bq, nullptr, 0);
    proj_mma_kernel<<<ggrid, 256>>>(key,   Wk, bk, nullptr, 1);
    proj_mma_kernel<<<ggrid, 256>>>(value, Wv, bv, nullptr, 2);

    dim3 agrid(SEQ / 64, BATCH * N_HEADS);      // (32, 64)
    attn_tc_kernel<<<agrid, 128, ATTN_TC_SMEM>>>();

    proj_mma_kernel<<<ggrid, 256>>>(nullptr, Wo, bo, out, 3);
}

// round 15
// speedup vs baseline: 2.8735x; 1.0002x over previous
#include <cuda_runtime.h>
#include <stdint.h>
#include <math.h>

#define D_MODEL 1024
#define N_HEADS 16
#define HEAD_DIM 64
#define BATCH 4
#define SEQ 2048
#define M_TOTAL (BATCH * SEQ)   // 8192

// Scratch (device globals — allocation-free per harness rules)
__device__ float g_Q[BATCH * N_HEADS * SEQ * HEAD_DIM];   // [B,H,S,Dh]
__device__ float g_K[BATCH * N_HEADS * SEQ * HEAD_DIM];
__device__ float g_V[BATCH * N_HEADS * SEQ * HEAD_DIM];
__device__ float g_attn[M_TOTAL * D_MODEL];               // [B,S,D]

// ===========================================================================
// Portable tensor-core helpers (mma.sync, sm_80+ PTX — no 'a'-gated features)
// ===========================================================================
__device__ __forceinline__ uint32_t f2tf32(float x) {
    uint32_t r;
    asm("cvt.rna.tf32.f32 %0, %1;" : "=r"(r) : "f"(x));
    return r;
}

// D(16x8) += A(16x8, row) * B(8x8, col)   tf32 inputs, fp32 accumulate
__device__ __forceinline__ void mma_tf32(float c[4],
                                         uint32_t a0, uint32_t a1,
                                         uint32_t a2, uint32_t a3,
                                         uint32_t b0, uint32_t b1)
{
    asm volatile(
        "mma.sync.aligned.m16n8k8.row.col.f32.tf32.tf32.f32 "
        "{%0,%1,%2,%3}, {%4,%5,%6,%7}, {%8,%9}, {%0,%1,%2,%3};"
        : "+f"(c[0]), "+f"(c[1]), "+f"(c[2]), "+f"(c[3])
        : "r"(a0), "r"(a1), "r"(a2), "r"(a3), "r"(b0), "r"(b1));
}

__device__ __forceinline__ void mma_tf32_f(float c[4],
                                           float a0, float a1,
                                           float a2, float a3,
                                           float b0, float b1)
{
    mma_tf32(c, __float_as_uint(a0), __float_as_uint(a1),
                __float_as_uint(a2), __float_as_uint(a3),
                __float_as_uint(b0), __float_as_uint(b1));
}

// ===========================================================================
// tf32 mma.sync GEMM (unchanged from the 2697us passing kernel).
// C[m,n] = sum_k X[m,k]*W[n,k] + bias[n]
// ===========================================================================
#define PAD 36

__global__ __launch_bounds__(256) void proj_mma_kernel(
    const float* __restrict__ Xin, const float* __restrict__ W,
    const float* __restrict__ bias, float* __restrict__ Cout, int mode)
{
    __shared__ uint32_t As[128 * PAD];
    __shared__ uint32_t Bs[128 * PAD];

    const float* X = (mode == 3) ? g_attn : Xin;

    const int tid  = threadIdx.x;
    const int lane = tid & 31;
    const int wid  = tid >> 5;
    const int wm   = wid & 1;
    const int wn   = wid >> 1;
    const int m0 = blockIdx.y * 128;
    const int n0 = blockIdx.x * 128;

    const int grp = lane >> 2;
    const int qid = lane & 3;

    float acc[4][4][4];
#pragma unroll
    for (int mt = 0; mt < 4; mt++)
#pragma unroll
        for (int nt = 0; nt < 4; nt++)
#pragma unroll
            for (int e = 0; e < 4; e++) acc[mt][nt][e] = 0.0f;

    int rowi[4], c4i[4];
#pragma unroll
    for (int i = 0; i < 4; i++) {
        const int f = tid + i * 256;
        rowi[i] = f >> 3;
        c4i[i]  = (f & 7) * 4;
    }

    float4 pa[4], pb[4];
#pragma unroll
    for (int i = 0; i < 4; i++) {
        pa[i] = *(const float4*)(X + (size_t)(m0 + rowi[i]) * D_MODEL + c4i[i]);
        pb[i] = *(const float4*)(W + (size_t)(n0 + rowi[i]) * D_MODEL + c4i[i]);
    }

    for (int j = 0; j < 32; j++) {
#pragma unroll
        for (int i = 0; i < 4; i++) {
            uint4 at = make_uint4(f2tf32(pa[i].x), f2tf32(pa[i].y),
                                  f2tf32(pa[i].z), f2tf32(pa[i].w));
            uint4 bt = make_uint4(f2tf32(pb[i].x), f2tf32(pb[i].y),
                                  f2tf32(pb[i].z), f2tf32(pb[i].w));
            *(uint4*)(As + rowi[i] * PAD + c4i[i]) = at;
            *(uint4*)(Bs + rowi[i] * PAD + c4i[i]) = bt;
        }
        __syncthreads();

        if (j < 31) {
            const int k0n = (j + 1) * 32;
#pragma unroll
            for (int i = 0; i < 4; i++) {
                pa[i] = *(const float4*)(X + (size_t)(m0 + rowi[i]) * D_MODEL + k0n + c4i[i]);
                pb[i] = *(const float4*)(W + (size_t)(n0 + rowi[i]) * D_MODEL + k0n + c4i[i]);
            }
        }

#pragma unroll
        for (int ks = 0; ks < 4; ks++) {
            const int kc = ks * 8 + qid;
            uint32_t af[4][4];
#pragma unroll
            for (int mt = 0; mt < 4; mt++) {
                const int ar = (wm * 64 + mt * 16 + grp) * PAD;
                af[mt][0] = As[ar + kc];
                af[mt][1] = As[ar + 8 * PAD + kc];
                af[mt][2] = As[ar + kc + 4];
                af[mt][3] = As[ar + 8 * PAD + kc + 4];
            }
            uint32_t bf[4][2];
#pragma unroll
            for (int nt = 0; nt < 4; nt++) {
                const int br = (wn * 32 + nt * 8 + grp) * PAD;
                bf[nt][0] = Bs[br + kc];
                bf[nt][1] = Bs[br + kc + 4];
            }
#pragma unroll
            for (int mt = 0; mt < 4; mt++)
#pragma unroll
                for (int nt = 0; nt < 4; nt++)
                    mma_tf32(acc[mt][nt], af[mt][0], af[mt][1], af[mt][2],
                             af[mt][3], bf[nt][0], bf[nt][1]);
        }
        __syncthreads();
    }

    float* dst = (mode == 0) ? g_Q : (mode == 1) ? g_K : g_V;
#pragma unroll
    for (int mt = 0; mt < 4; mt++) {
#pragma unroll
        for (int nt = 0; nt < 4; nt++) {
            const int n = n0 + wn * 32 + nt * 8 + qid * 2;
            const float2 b2 = *(const float2*)(bias + n);
#pragma unroll
            for (int half = 0; half < 2; half++) {
                const int m = m0 + wm * 64 + mt * 16 + grp + half * 8;
                float2 v;
                v.x = acc[mt][nt][half * 2 + 0] + b2.x;
                v.y = acc[mt][nt][half * 2 + 1] + b2.y;
                if (mode == 3) {
                    *(float2*)(Cout + (size_t)m * D_MODEL + n) = v;
                } else {
                    const int bb = m >> 11, s = m & 2047;
                    const int h  = n >> 6,  dh = n & 63;
                    *(float2*)(dst + (((size_t)(bb * N_HEADS + h) * SEQ + s)
                                      * HEAD_DIM) + dh) = v;
                }
            }
        }
    }
}

// ===========================================================================
// Tensor-core flash attention (tf32 mma.sync).
// Per (b,h): Q[2048,64], K[2048,64], V[2048,64].
// CTA: 128 thr = 4 warps; Br=64 (16 q-rows per warp), Bc=64.
// QK^T: split-precision 3xTF32 (fp32-accurate scores).
// PV:   plain tf32; row-sum l computed from tf32-rounded P so P-rounding
//       cancels in normalization.
// SMEM stride 68 -> conflict-free fragment loads (banks 4*grp+qid distinct).
// ===========================================================================
#define AT_PAD  68
#define AT_TILE (64 * AT_PAD)
#define ATTN_TC_SMEM (6 * AT_TILE * 4)   // 104448 B -> 2 CTAs/SM

__global__ __launch_bounds__(128) void attn_tc_kernel()
{
    extern __shared__ float smf[];
    float* Qhi = smf;
    float* Qlo = Qhi + AT_TILE;
    float* Khi = Qlo + AT_TILE;
    float* Klo = Khi + AT_TILE;
    float* Vs  = Klo + AT_TILE;   // row-major [c][d], tf32 values
    float* Ps  = Vs  + AT_TILE;   // [r][c], tf32 values

    const int tid  = threadIdx.x;
    const int warp = tid >> 5;
    const int lane = tid & 31;
    const int grp  = lane >> 2;   // 0..7
    const int qid  = lane & 3;    // 0..3
    const int bh = blockIdx.y;
    const int q0 = blockIdx.x * 64;

    const float* Qg = g_Q + (size_t)bh * SEQ * HEAD_DIM + (size_t)q0 * HEAD_DIM;
    const float* Kg = g_K + (size_t)bh * SEQ * HEAD_DIM;
    const float* Vg = g_V + (size_t)bh * SEQ * HEAD_DIM;

    // Load Q tile once: scale by 1/8 (exact), split into tf32 hi + lo.
#pragma unroll
    for (int i = 0; i < 8; i++) {
        const int f = tid + i * 128;          // 0..1023 float4 slots
        const int row = f >> 4, c4 = (f & 15) * 4;
        float4 q = *(const float4*)(Qg + row * 64 + c4);
        q.x *= 0.125f; q.y *= 0.125f; q.z *= 0.125f; q.w *= 0.125f;
        float4 hi, lo;
        hi.x = __uint_as_float(f2tf32(q.x)); lo.x = __uint_as_float(f2tf32(q.x - hi.x));
        hi.y = __uint_as_float(f2tf32(q.y)); lo.y = __uint_as_float(f2tf32(q.y - hi.y));
        hi.z = __uint_as_float(f2tf32(q.z)); lo.z = __uint_as_float(f2tf32(q.z - hi.z));
        hi.w = __uint_as_float(f2tf32(q.w)); lo.w = __uint_as_float(f2tf32(q.w - hi.w));
        *(float4*)(Qhi + row * AT_PAD + c4) = hi;
        *(float4*)(Qlo + row * AT_PAD + c4) = lo;
    }

    float m_run[2] = { -1e30f, -1e30f };
    float l_run[2] = { 0.0f, 0.0f };
    float oacc[8][4];
#pragma unroll
    for (int nt = 0; nt < 8; nt++)
#pragma unroll
        for (int e = 0; e < 4; e++) oacc[nt][e] = 0.0f;

    const int arow = (warp * 16 + grp) * AT_PAD;   // this thread's A-frag row base

    for (int kt = 0; kt < SEQ / 64; kt++) {
        // ---- gmem -> regs ----
        float4 kv[8], vv[8];
#pragma unroll
        for (int i = 0; i < 8; i++) {
            const int f = tid + i * 128;
            const int row = f >> 4, c4 = (f & 15) * 4;
            kv[i] = *(const float4*)(Kg + (size_t)(kt * 64 + row) * 64 + c4);
            vv[i] = *(const float4*)(Vg + (size_t)(kt * 64 + row) * 64 + c4);
        }
        __syncthreads();   // all warps done reading previous K/V/Ps tiles
        // ---- regs -> smem: split K, convert V ----
#pragma unroll
        for (int i = 0; i < 8; i++) {
            const int f = tid + i * 128;
            const int row = f >> 4, c4 = (f & 15) * 4;
            float4 hi, lo;
            hi.x = __uint_as_float(f2tf32(kv[i].x)); lo.x = __uint_as_float(f2tf32(kv[i].x - hi.x));
            hi.y = __uint_as_float(f2tf32(kv[i].y)); lo.y = __uint_as_float(f2tf32(kv[i].y - hi.y));
            hi.z = __uint_as_float(f2tf32(kv[i].z)); lo.z = __uint_as_float(f2tf32(kv[i].z - hi.z));
            hi.w = __uint_as_float(f2tf32(kv[i].w)); lo.w = __uint_as_float(f2tf32(kv[i].w - hi.w));
            *(float4*)(Khi + row * AT_PAD + c4) = hi;
            *(float4*)(Klo + row * AT_PAD + c4) = lo;
            float4 vt;
            vt.x = __uint_as_float(f2tf32(vv[i].x));
            vt.y = __uint_as_float(f2tf32(vv[i].y));
            vt.z = __uint_as_float(f2tf32(vv[i].z));
            vt.w = __uint_as_float(f2tf32(vv[i].w));
            *(float4*)(Vs + row * AT_PAD + c4) = vt;
        }
        __syncthreads();

        // ---- S = (Q/8) K^T, split 3xTF32 ----
        float sacc[8][4];
#pragma unroll
        for (int nt = 0; nt < 8; nt++)
#pragma unroll
            for (int e = 0; e < 4; e++) sacc[nt][e] = 0.0f;

#pragma unroll
        for (int ks = 0; ks < 8; ks++) {
            const int kc = ks * 8 + qid;
            const float ah0 = Qhi[arow + kc],            ah1 = Qhi[arow + 8 * AT_PAD + kc];
            const float ah2 = Qhi[arow + kc + 4],        ah3 = Qhi[arow + 8 * AT_PAD + kc + 4];
            const float al0 = Qlo[arow + kc],            al1 = Qlo[arow + 8 * AT_PAD + kc];
            const float al2 = Qlo[arow + kc + 4],        al3 = Qlo[arow + 8 * AT_PAD + kc + 4];
#pragma unroll
            for (int nt = 0; nt < 8; nt++) {
                const int br = (nt * 8 + grp) * AT_PAD;
                const float bh0 = Khi[br + kc], bh1 = Khi[br + kc + 4];
                const float bl0 = Klo[br + kc], bl1 = Klo[br + kc + 4];
                mma_tf32_f(sacc[nt], al0, al1, al2, al3, bh0, bh1);  // Qlo*Khi
                mma_tf32_f(sacc[nt], ah0, ah1, ah2, ah3, bl0, bl1);  // Qhi*Klo
                mma_tf32_f(sacc[nt], ah0, ah1, ah2, ah3, bh0, bh1);  // Qhi*Khi
            }
        }

        // ---- online softmax (rows grp, grp+8 of this warp's 16) ----
        float mx0 = -1e30f, mx1 = -1e30f;
#pragma unroll
        for (int nt = 0; nt < 8; nt++) {
            mx0 = fmaxf(mx0, fmaxf(sacc[nt][0], sacc[nt][1]));
            mx1 = fmaxf(mx1, fmaxf(sacc[nt][2], sacc[nt][3]));
        }
        mx0 = fmaxf(mx0, __shfl_xor_sync(0xffffffffu, mx0, 1));
        mx0 = fmaxf(mx0, __shfl_xor_sync(0xffffffffu, mx0, 2));
        mx1 = fmaxf(mx1, __shfl_xor_sync(0xffffffffu, mx1, 1));
        mx1 = fmaxf(mx1, __shfl_xor_sync(0xffffffffu, mx1, 2));

        const float mn0 = fmaxf(m_run[0], mx0);
        const float mn1 = fmaxf(m_run[1], mx1);
        const float alpha0 = __expf(m_run[0] - mn0);
        const float alpha1 = __expf(m_run[1] - mn1);
        m_run[0] = mn0; m_run[1] = mn1;

        float ls0 = 0.0f, ls1 = 0.0f;
#pragma unroll
        for (int nt = 0; nt < 8; nt++) {
            const float p0 = __uint_as_float(f2tf32(__expf(sacc[nt][0] - mn0)));
            const float p1 = __uint_as_float(f2tf32(__expf(sacc[nt][1] - mn0)));
            const float p2 = __uint_as_float(f2tf32(__expf(sacc[nt][2] - mn1)));
            const float p3 = __uint_as_float(f2tf32(__expf(sacc[nt][3] - mn1)));
            ls0 += p0 + p1;
            ls1 += p2 + p3;
            *(float2*)(Ps + arow + nt * 8 + 2 * qid)               = make_float2(p0, p1);
            *(float2*)(Ps + arow + 8 * AT_PAD + nt * 8 + 2 * qid)  = make_float2(p2, p3);
        }
        ls0 += __shfl_xor_sync(0xffffffffu, ls0, 1);
        ls0 += __shfl_xor_sync(0xffffffffu, ls0, 2);
        ls1 += __shfl_xor_sync(0xffffffffu, ls1, 1);
        ls1 += __shfl_xor_sync(0xffffffffu, ls1, 2);
        l_run[0] = l_run[0] * alpha0 + ls0;
        l_run[1] = l_run[1] * alpha1 + ls1;

#pragma unroll
        for (int nt = 0; nt < 8; nt++) {
            oacc[nt][0] *= alpha0; oacc[nt][1] *= alpha0;
            oacc[nt][2] *= alpha1; oacc[nt][3] *= alpha1;
        }
        __syncwarp();   // Ps rows are warp-private; order stores before loads

        // ---- O += P V ----
#pragma unroll
        for (int ks = 0; ks < 8; ks++) {
            const int kc = ks * 8 + qid;
            const float a0 = Ps[arow + kc],     a1 = Ps[arow + 8 * AT_PAD + kc];
            const float a2 = Ps[arow + kc + 4], a3 = Ps[arow + 8 * AT_PAD + kc + 4];
#pragma unroll
            for (int nt = 0; nt < 8; nt++) {
                const float b0 = Vs[(ks * 8 + qid) * AT_PAD + nt * 8 + grp];
                const float b1 = Vs[(ks * 8 + qid + 4) * AT_PAD + nt * 8 + grp];
                mma_tf32_f(oacc[nt], a0, a1, a2, a3, b0, b1);
            }
        }
    }

    // ---- epilogue: normalize, scatter into [B,S,D] ----
    const float inv0 = 1.0f / l_run[0];
    const float inv1 = 1.0f / l_run[1];
    const int b = bh >> 4, h = bh & 15;
    const int row0 = q0 + warp * 16 + grp;
    const int row1 = row0 + 8;
    float* o0 = g_attn + ((size_t)(b * SEQ + row0)) * D_MODEL + h * HEAD_DIM;
    float* o1 = g_attn + ((size_t)(b * SEQ + row1)) * D_MODEL + h * HEAD_DIM;
#pragma unroll
    for (int nt = 0; nt < 8; nt++) {
        const int d = nt * 8 + 2 * qid;
        *(float2*)(o0 + d) = make_float2(oacc[nt][0] * inv0, oacc[nt][1] * inv0);
        *(float2*)(o1 + d) = make_float2(oacc[nt][2] * inv1, oacc[nt][3] * inv1);
    }
}

// ---------------------------------------------------------------------------
extern "C" void kernel_launch(void* const* d_in, const int* in_sizes, int n_in,
                              void* d_out, int out_size)
{
    (void)in_sizes; (void)n_in; (void)out_size;
    const float* query = (const float*)d_in[0];
    const float* key   = (const float*)d_in[1];
    const float* value = (const float*)d_in[2];
    const float* Wq    = (const float*)d_in[3];
    const float* bq    = (const float*)d_in[4];
    const float* Wk    = (const float*)d_in[5];
    const float* bk    = (const float*)d_in[6];
    const float* Wv    = (const float*)d_in[7];
    const float* bv    = (const float*)d_in[8];
    const float* Wo    = (const float*)d_in[9];
    const float* bo    = (const float*)d_in[10];
    float* out = (float*)d_out;

    cudaFuncSetAttribute(attn_tc_kernel,
                         cudaFuncAttributeMaxDynamicSharedMemorySize,
                         ATTN_TC_SMEM);

    dim3 ggrid(D_MODEL / 128, M_TOTAL / 128);   // (8, 64)
    proj_mma_kernel<<<ggrid, 256>>>(query, Wq, bq, nullptr, 0);
    proj_mma_kernel<<<ggrid, 256>>>(key,   Wk, bk, nullptr, 1);
    proj_mma_kernel<<<ggrid, 256>>>(value, Wv, bv, nullptr, 2);

    dim3 agrid(SEQ / 64, BATCH * N_HEADS);      // (32, 64)
    attn_tc_kernel<<<agrid, 128, ATTN_TC_SMEM>>>();

    proj_mma_kernel<<<ggrid, 256>>>(nullptr, Wo, bo, out, 3);
}

// round 16
// speedup vs baseline: 3.3846x; 1.1779x over previous
#include <cuda_runtime.h>
#include <stdint.h>
#include <math.h>

#define D_MODEL 1024
#define N_HEADS 16
#define HEAD_DIM 64
#define BATCH 4
#define SEQ 2048
#define M_TOTAL (BATCH * SEQ)   // 8192

// Scratch (device globals — allocation-free per harness rules)
__device__ float g_Q[BATCH * N_HEADS * SEQ * HEAD_DIM];   // [B,H,S,Dh]
__device__ float g_K[BATCH * N_HEADS * SEQ * HEAD_DIM];
__device__ float g_V[BATCH * N_HEADS * SEQ * HEAD_DIM];
__device__ float g_attn[M_TOTAL * D_MODEL];               // [B,S,D]

// ===========================================================================
// Portable tensor-core helpers (mma.sync, sm_80+ PTX — no 'a'-gated features)
// ===========================================================================
__device__ __forceinline__ uint32_t f2tf32(float x) {
    uint32_t r;
    asm("cvt.rna.tf32.f32 %0, %1;" : "=r"(r) : "f"(x));
    return r;
}

// D(16x8) += A(16x8, row) * B(8x8, col)   tf32 inputs, fp32 accumulate
__device__ __forceinline__ void mma_tf32(float c[4],
                                         uint32_t a0, uint32_t a1,
                                         uint32_t a2, uint32_t a3,
                                         uint32_t b0, uint32_t b1)
{
    asm volatile(
        "mma.sync.aligned.m16n8k8.row.col.f32.tf32.tf32.f32 "
        "{%0,%1,%2,%3}, {%4,%5,%6,%7}, {%8,%9}, {%0,%1,%2,%3};"
        : "+f"(c[0]), "+f"(c[1]), "+f"(c[2]), "+f"(c[3])
        : "r"(a0), "r"(a1), "r"(a2), "r"(a3), "r"(b0), "r"(b1));
}

__device__ __forceinline__ void mma_tf32_f(float c[4],
                                           float a0, float a1,
                                           float a2, float a3,
                                           float b0, float b1)
{
    mma_tf32(c, __float_as_uint(a0), __float_as_uint(a1),
                __float_as_uint(a2), __float_as_uint(a3),
                __float_as_uint(b0), __float_as_uint(b1));
}

// ===========================================================================
// tf32 mma.sync GEMM (unchanged from the 2697us passing kernel).
// C[m,n] = sum_k X[m,k]*W[n,k] + bias[n]
// ===========================================================================
#define PAD 36

__global__ __launch_bounds__(256) void proj_mma_kernel(
    const float* __restrict__ Xin, const float* __restrict__ W,
    const float* __restrict__ bias, float* __restrict__ Cout, int mode)
{
    __shared__ uint32_t As[128 * PAD];
    __shared__ uint32_t Bs[128 * PAD];

    const float* X = (mode == 3) ? g_attn : Xin;

    const int tid  = threadIdx.x;
    const int lane = tid & 31;
    const int wid  = tid >> 5;
    const int wm   = wid & 1;
    const int wn   = wid >> 1;
    const int m0 = blockIdx.y * 128;
    const int n0 = blockIdx.x * 128;

    const int grp = lane >> 2;
    const int qid = lane & 3;

    float acc[4][4][4];
#pragma unroll
    for (int mt = 0; mt < 4; mt++)
#pragma unroll
        for (int nt = 0; nt < 4; nt++)
#pragma unroll
            for (int e = 0; e < 4; e++) acc[mt][nt][e] = 0.0f;

    int rowi[4], c4i[4];
#pragma unroll
    for (int i = 0; i < 4; i++) {
        const int f = tid + i * 256;
        rowi[i] = f >> 3;
        c4i[i]  = (f & 7) * 4;
    }

    float4 pa[4], pb[4];
#pragma unroll
    for (int i = 0; i < 4; i++) {
        pa[i] = *(const float4*)(X + (size_t)(m0 + rowi[i]) * D_MODEL + c4i[i]);
        pb[i] = *(const float4*)(W + (size_t)(n0 + rowi[i]) * D_MODEL + c4i[i]);
    }

    for (int j = 0; j < 32; j++) {
#pragma unroll
        for (int i = 0; i < 4; i++) {
            uint4 at = make_uint4(f2tf32(pa[i].x), f2tf32(pa[i].y),
                                  f2tf32(pa[i].z), f2tf32(pa[i].w));
            uint4 bt = make_uint4(f2tf32(pb[i].x), f2tf32(pb[i].y),
                                  f2tf32(pb[i].z), f2tf32(pb[i].w));
            *(uint4*)(As + rowi[i] * PAD + c4i[i]) = at;
            *(uint4*)(Bs + rowi[i] * PAD + c4i[i]) = bt;
        }
        __syncthreads();

        if (j < 31) {
            const int k0n = (j + 1) * 32;
#pragma unroll
            for (int i = 0; i < 4; i++) {
                pa[i] = *(const float4*)(X + (size_t)(m0 + rowi[i]) * D_MODEL + k0n + c4i[i]);
                pb[i] = *(const float4*)(W + (size_t)(n0 + rowi[i]) * D_MODEL + k0n + c4i[i]);
            }
        }

#pragma unroll
        for (int ks = 0; ks < 4; ks++) {
            const int kc = ks * 8 + qid;
            uint32_t af[4][4];
#pragma unroll
            for (int mt = 0; mt < 4; mt++) {
                const int ar = (wm * 64 + mt * 16 + grp) * PAD;
                af[mt][0] = As[ar + kc];
                af[mt][1] = As[ar + 8 * PAD + kc];
                af[mt][2] = As[ar + kc + 4];
                af[mt][3] = As[ar + 8 * PAD + kc + 4];
            }
            uint32_t bf[4][2];
#pragma unroll
            for (int nt = 0; nt < 4; nt++) {
                const int br = (wn * 32 + nt * 8 + grp) * PAD;
                bf[nt][0] = Bs[br + kc];
                bf[nt][1] = Bs[br + kc + 4];
            }
#pragma unroll
            for (int mt = 0; mt < 4; mt++)
#pragma unroll
                for (int nt = 0; nt < 4; nt++)
                    mma_tf32(acc[mt][nt], af[mt][0], af[mt][1], af[mt][2],
                             af[mt][3], bf[nt][0], bf[nt][1]);
        }
        __syncthreads();
    }

    float* dst = (mode == 0) ? g_Q : (mode == 1) ? g_K : g_V;
#pragma unroll
    for (int mt = 0; mt < 4; mt++) {
#pragma unroll
        for (int nt = 0; nt < 4; nt++) {
            const int n = n0 + wn * 32 + nt * 8 + qid * 2;
            const float2 b2 = *(const float2*)(bias + n);
#pragma unroll
            for (int half = 0; half < 2; half++) {
                const int m = m0 + wm * 64 + mt * 16 + grp + half * 8;
                float2 v;
                v.x = acc[mt][nt][half * 2 + 0] + b2.x;
                v.y = acc[mt][nt][half * 2 + 1] + b2.y;
                if (mode == 3) {
                    *(float2*)(Cout + (size_t)m * D_MODEL + n) = v;
                } else {
                    const int bb = m >> 11, s = m & 2047;
                    const int h  = n >> 6,  dh = n & 63;
                    *(float2*)(dst + (((size_t)(bb * N_HEADS + h) * SEQ + s)
                                      * HEAD_DIM) + dh) = v;
                }
            }
        }
    }
}

// ===========================================================================
// Tensor-core flash attention v2 (tf32 mma.sync).
// CTA: 128 thr = 4 warps; Br=64 (16 q-rows/warp), Bc=64.
// QK^T: 2-term split — S = (Qhi + Qlo) * tf32(K). Q decomposition is exact,
//       only K is tf32-rounded (score err ~2.4e-4 absolute).
// Q fragments (hi+lo) hoisted to registers: loop-invariant, staged once
//       through smem temps -> zero QK A-frag LDS in the main loop.
// PV:   plain tf32; row-sum l computed from tf32-rounded P (P-rounding
//       cancels in normalization).
// SMEM: 3 tiles (Khi, Vs, Ps) = 52.2KB -> 3 CTAs/SM.
// ===========================================================================
#define AT_PAD  68
#define AT_TILE (64 * AT_PAD)
#define ATTN_TC_SMEM (3 * AT_TILE * 4)   // 52224 B

__global__ __launch_bounds__(128, 3) void attn_tc_kernel()
{
    extern __shared__ float smf[];
    float* Khi = smf;                 // K tile (tf32), also Q-hi staging temp
    float* Vs  = Khi + AT_TILE;       // V tile (tf32) [c][d]
    float* Ps  = Vs  + AT_TILE;       // P tile [r][c], also Q-lo staging temp

    const int tid  = threadIdx.x;
    const int warp = tid >> 5;
    const int lane = tid & 31;
    const int grp  = lane >> 2;   // 0..7
    const int qid  = lane & 3;    // 0..3
    const int bh = blockIdx.y;
    const int q0 = blockIdx.x * 64;

    const float* Qg = g_Q + (size_t)bh * SEQ * HEAD_DIM + (size_t)q0 * HEAD_DIM;
    const float* Kg = g_K + (size_t)bh * SEQ * HEAD_DIM;
    const float* Vg = g_V + (size_t)bh * SEQ * HEAD_DIM;

    // ---- stage Q once: scale 1/8 (exact), split; hi->Khi, lo->Ps (temps) ----
#pragma unroll
    for (int i = 0; i < 8; i++) {
        const int f = tid + i * 128;          // 1024 float4 slots
        const int row = f >> 4, c4 = (f & 15) * 4;
        float4 q = *(const float4*)(Qg + row * 64 + c4);
        q.x *= 0.125f; q.y *= 0.125f; q.z *= 0.125f; q.w *= 0.125f;
        float4 hi, lo;
        hi.x = __uint_as_float(f2tf32(q.x)); lo.x = __uint_as_float(f2tf32(q.x - hi.x));
        hi.y = __uint_as_float(f2tf32(q.y)); lo.y = __uint_as_float(f2tf32(q.y - hi.y));
        hi.z = __uint_as_float(f2tf32(q.z)); lo.z = __uint_as_float(f2tf32(q.z - hi.z));
        hi.w = __uint_as_float(f2tf32(q.w)); lo.w = __uint_as_float(f2tf32(q.w - hi.w));
        *(float4*)(Khi + row * AT_PAD + c4) = hi;
        *(float4*)(Ps  + row * AT_PAD + c4) = lo;
    }
    __syncthreads();

    // ---- extract this thread's Q A-fragments into registers (invariant) ----
    const int arow = (warp * 16 + grp) * AT_PAD;
    float qh[8][4], ql[8][4];
#pragma unroll
    for (int ks = 0; ks < 8; ks++) {
        const int kc = ks * 8 + qid;
        qh[ks][0] = Khi[arow + kc];
        qh[ks][1] = Khi[arow + 8 * AT_PAD + kc];
        qh[ks][2] = Khi[arow + kc + 4];
        qh[ks][3] = Khi[arow + 8 * AT_PAD + kc + 4];
        ql[ks][0] = Ps[arow + kc];
        ql[ks][1] = Ps[arow + 8 * AT_PAD + kc];
        ql[ks][2] = Ps[arow + kc + 4];
        ql[ks][3] = Ps[arow + 8 * AT_PAD + kc + 4];
    }

    float m_run[2] = { -1e30f, -1e30f };
    float l_run[2] = { 0.0f, 0.0f };
    float oacc[8][4];
#pragma unroll
    for (int nt = 0; nt < 8; nt++)
#pragma unroll
        for (int e = 0; e < 4; e++) oacc[nt][e] = 0.0f;

    for (int kt = 0; kt < SEQ / 64; kt++) {
        // ---- K batch: gmem -> regs -> smem (tf32) ----
        float4 st[8];
#pragma unroll
        for (int i = 0; i < 8; i++) {
            const int f = tid + i * 128;
            const int row = f >> 4, c4 = (f & 15) * 4;
            st[i] = *(const float4*)(Kg + (size_t)(kt * 64 + row) * 64 + c4);
        }
        __syncthreads();   // all warps done with prev Khi/Vs/Ps (incl. Q temps)
#pragma unroll
        for (int i = 0; i < 8; i++) {
            const int f = tid + i * 128;
            const int row = f >> 4, c4 = (f & 15) * 4;
            float4 t;
            t.x = __uint_as_float(f2tf32(st[i].x));
            t.y = __uint_as_float(f2tf32(st[i].y));
            t.z = __uint_as_float(f2tf32(st[i].z));
            t.w = __uint_as_float(f2tf32(st[i].w));
            *(float4*)(Khi + row * AT_PAD + c4) = t;
        }
        // ---- V batch ----
#pragma unroll
        for (int i = 0; i < 8; i++) {
            const int f = tid + i * 128;
            const int row = f >> 4, c4 = (f & 15) * 4;
            st[i] = *(const float4*)(Vg + (size_t)(kt * 64 + row) * 64 + c4);
        }
#pragma unroll
        for (int i = 0; i < 8; i++) {
            const int f = tid + i * 128;
            const int row = f >> 4, c4 = (f & 15) * 4;
            float4 t;
            t.x = __uint_as_float(f2tf32(st[i].x));
            t.y = __uint_as_float(f2tf32(st[i].y));
            t.z = __uint_as_float(f2tf32(st[i].z));
            t.w = __uint_as_float(f2tf32(st[i].w));
            *(float4*)(Vs + row * AT_PAD + c4) = t;
        }
        __syncthreads();

        // ---- S = (Qhi + Qlo) K^T ----
        float sacc[8][4];
#pragma unroll
        for (int nt = 0; nt < 8; nt++)
#pragma unroll
            for (int e = 0; e < 4; e++) sacc[nt][e] = 0.0f;

#pragma unroll
        for (int ks = 0; ks < 8; ks++) {
            const int kc = ks * 8 + qid;
#pragma unroll
            for (int nt = 0; nt < 8; nt++) {
                const int br = (nt * 8 + grp) * AT_PAD;
                const float bh0 = Khi[br + kc], bh1 = Khi[br + kc + 4];
                mma_tf32_f(sacc[nt], ql[ks][0], ql[ks][1], ql[ks][2], ql[ks][3],
                           bh0, bh1);
                mma_tf32_f(sacc[nt], qh[ks][0], qh[ks][1], qh[ks][2], qh[ks][3],
                           bh0, bh1);
            }
        }

        // ---- online softmax (rows grp, grp+8 of this warp's 16) ----
        float mx0 = -1e30f, mx1 = -1e30f;
#pragma unroll
        for (int nt = 0; nt < 8; nt++) {
            mx0 = fmaxf(mx0, fmaxf(sacc[nt][0], sacc[nt][1]));
            mx1 = fmaxf(mx1, fmaxf(sacc[nt][2], sacc[nt][3]));
        }
        mx0 = fmaxf(mx0, __shfl_xor_sync(0xffffffffu, mx0, 1));
        mx0 = fmaxf(mx0, __shfl_xor_sync(0xffffffffu, mx0, 2));
        mx1 = fmaxf(mx1, __shfl_xor_sync(0xffffffffu, mx1, 1));
        mx1 = fmaxf(mx1, __shfl_xor_sync(0xffffffffu, mx1, 2));

        const float mn0 = fmaxf(m_run[0], mx0);
        const float mn1 = fmaxf(m_run[1], mx1);
        const float alpha0 = __expf(m_run[0] - mn0);
        const float alpha1 = __expf(m_run[1] - mn1);
        m_run[0] = mn0; m_run[1] = mn1;

        float ls0 = 0.0f, ls1 = 0.0f;
#pragma unroll
        for (int nt = 0; nt < 8; nt++) {
            const float p0 = __uint_as_float(f2tf32(__expf(sacc[nt][0] - mn0)));
            const float p1 = __uint_as_float(f2tf32(__expf(sacc[nt][1] - mn0)));
            const float p2 = __uint_as_float(f2tf32(__expf(sacc[nt][2] - mn1)));
            const float p3 = __uint_as_float(f2tf32(__expf(sacc[nt][3] - mn1)));
            ls0 += p0 + p1;
            ls1 += p2 + p3;
            *(float2*)(Ps + arow + nt * 8 + 2 * qid)              = make_float2(p0, p1);
            *(float2*)(Ps + arow + 8 * AT_PAD + nt * 8 + 2 * qid) = make_float2(p2, p3);
        }
        ls0 += __shfl_xor_sync(0xffffffffu, ls0, 1);
        ls0 += __shfl_xor_sync(0xffffffffu, ls0, 2);
        ls1 += __shfl_xor_sync(0xffffffffu, ls1, 1);
        ls1 += __shfl_xor_sync(0xffffffffu, ls1, 2);
        l_run[0] = l_run[0] * alpha0 + ls0;
        l_run[1] = l_run[1] * alpha1 + ls1;

#pragma unroll
        for (int nt = 0; nt < 8; nt++) {
            oacc[nt][0] *= alpha0; oacc[nt][1] *= alpha0;
            oacc[nt][2] *= alpha1; oacc[nt][3] *= alpha1;
        }
        __syncwarp();   // Ps rows are warp-private; order stores before loads

        // ---- O += P V ----
#pragma unroll
        for (int ks = 0; ks < 8; ks++) {
            const int kc = ks * 8 + qid;
            const float a0 = Ps[arow + kc],     a1 = Ps[arow + 8 * AT_PAD + kc];
            const float a2 = Ps[arow + kc + 4], a3 = Ps[arow + 8 * AT_PAD + kc + 4];
#pragma unroll
            for (int nt = 0; nt < 8; nt++) {
                const float b0 = Vs[(ks * 8 + qid) * AT_PAD + nt * 8 + grp];
                const float b1 = Vs[(ks * 8 + qid + 4) * AT_PAD + nt * 8 + grp];
                mma_tf32_f(oacc[nt], a0, a1, a2, a3, b0, b1);
            }
        }
    }

    // ---- epilogue: normalize, scatter into [B,S,D] ----
    const float inv0 = 1.0f / l_run[0];
    const float inv1 = 1.0f / l_run[1];
    const int b = bh >> 4, h = bh & 15;
    const int row0 = q0 + warp * 16 + grp;
    const int row1 = row0 + 8;
    float* o0 = g_attn + ((size_t)(b * SEQ + row0)) * D_MODEL + h * HEAD_DIM;
    float* o1 = g_attn + ((size_t)(b * SEQ + row1)) * D_MODEL + h * HEAD_DIM;
#pragma unroll
    for (int nt = 0; nt < 8; nt++) {
        const int d = nt * 8 + 2 * qid;
        *(float2*)(o0 + d) = make_float2(oacc[nt][0] * inv0, oacc[nt][1] * inv0);
        *(float2*)(o1 + d) = make_float2(oacc[nt][2] * inv1, oacc[nt][3] * inv1);
    }
}

// ---------------------------------------------------------------------------
extern "C" void kernel_launch(void* const* d_in, const int* in_sizes, int n_in,
                              void* d_out, int out_size)
{
    (void)in_sizes; (void)n_in; (void)out_size;
    const float* query = (const float*)d_in[0];
    const float* key   = (const float*)d_in[1];
    const float* value = (const float*)d_in[2];
    const float* Wq    = (const float*)d_in[3];
    const float* bq    = (const float*)d_in[4];
    const float* Wk    = (const float*)d_in[5];
    const float* bk    = (const float*)d_in[6];
    const float* Wv    = (const float*)d_in[7];
    const float* bv    = (const float*)d_in[8];
    const float* Wo    = (const float*)d_in[9];
    const float* bo    = (const float*)d_in[10];
    float* out = (float*)d_out;

    cudaFuncSetAttribute(attn_tc_kernel,
                         cudaFuncAttributeMaxDynamicSharedMemorySize,
                         ATTN_TC_SMEM);

    dim3 ggrid(D_MODEL / 128, M_TOTAL / 128);   // (8, 64)
    proj_mma_kernel<<<ggrid, 256>>>(query, Wq, bq, nullptr, 0);
    proj_mma_kernel<<<ggrid, 256>>>(key,   Wk, bk, nullptr, 1);
    proj_mma_kernel<<<ggrid, 256>>>(value, Wv, bv, nullptr, 2);

    dim3 agrid(SEQ / 64, BATCH * N_HEADS);      // (32, 64)
    attn_tc_kernel<<<agrid, 128, ATTN_TC_SMEM>>>();

    proj_mma_kernel<<<ggrid, 256>>>(nullptr, Wo, bo, out, 3);
}